// round 1
// baseline (speedup 1.0000x reference)
#include <cuda_runtime.h>
#include <cuda_bf16.h>

// Problem constants (fixed by the dataset)
#define N_TIME   64
#define N_BATCH  8192
#define N_STATE  32
#define N_FORCE  16
#define DT_STEP  0.05f
// Picard (fixed-point) iterations per implicit step. Contraction factor ~0.1,
// warm-started from y_prev (initial error <= dt = 0.05) => 8 iters -> ~3e-9.
#define PICARD_ITERS 8

#define WARPS_PER_BLOCK 8
#define THREADS_PER_BLOCK (WARPS_PER_BLOCK * 32)

// Branchless accurate-enough tanh: (e^{2x}-1)/(e^{2x}+1).
// Clamp avoids inf/inf NaN; abs error ~1e-7 (vs 1e-3 gate after dt*63 amplification).
__device__ __forceinline__ float fast_tanh(float x) {
    x = fminf(fmaxf(x, -9.0f), 9.0f);
    float e = __expf(2.0f * x);
    return __fdividef(e - 1.0f, e + 1.0f);
}

__global__ __launch_bounds__(THREADS_PER_BLOCK)
void recsolve_kernel(const float* __restrict__ y0,
                     const float* __restrict__ forces,
                     const float* __restrict__ Wmat,
                     const float* __restrict__ Umat,
                     const float* __restrict__ bvec,
                     float* __restrict__ out)
{
    // One warp per batch element; lane = state index.
    __shared__ float ysh[WARPS_PER_BLOCK][2][N_STATE];  // double-buffered y exchange

    const int wib  = threadIdx.x >> 5;
    const int lane = threadIdx.x & 31;
    const int belt = blockIdx.x * WARPS_PER_BLOCK + wib;  // batch element [0,8192)

    // W row for this lane (32 regs), U row (16 regs), bias.
    float w[N_STATE];
#pragma unroll
    for (int j = 0; j < N_STATE; j++) w[j] = Wmat[lane * N_STATE + j];
    float ur[N_FORCE];
#pragma unroll
    for (int j = 0; j < N_FORCE; j++) ur[j] = Umat[lane * N_FORCE + j];
    const float bs = bvec[lane];

    float y_prev = y0[(size_t)belt * N_STATE + lane];
    // out[0] = y0 (output row 0 is the initial condition)
    out[(size_t)belt * N_STATE + lane] = y_prev;

    float* shbuf0 = ysh[wib][0];
    float* shbuf1 = ysh[wib][1];

    for (int t = 1; t < N_TIME; t++) {
        // f_u = U u_t + b  (u_t: 16 floats, staged in lanes 0..15, shfl-broadcast)
        const float* fptr = forces + ((size_t)t * N_BATCH + belt) * N_FORCE;
        float u_own = (lane < N_FORCE) ? fptr[lane] : 0.0f;
        float fu = bs;
#pragma unroll
        for (int j = 0; j < N_FORCE; j++)
            fu = fmaf(ur[j], __shfl_sync(0xffffffffu, u_own, j), fu);

        // Warm-started Picard iteration: y <- y_prev + dt*tanh(W y + fu)
        float y = y_prev;
#pragma unroll
        for (int it = 0; it < PICARD_ITERS; it++) {
            float* buf = (it & 1) ? shbuf1 : shbuf0;
            buf[lane] = y;
            __syncwarp();
            const float4* yv = (const float4*)buf;
            float acc0 = fu, acc1 = 0.0f;  // two chains to shorten the dep chain
#pragma unroll
            for (int jv = 0; jv < N_STATE / 8; jv++) {
                float4 a = yv[2 * jv + 0];
                float4 c = yv[2 * jv + 1];
                acc0 = fmaf(w[8 * jv + 0], a.x, acc0);
                acc1 = fmaf(w[8 * jv + 1], a.y, acc1);
                acc0 = fmaf(w[8 * jv + 2], a.z, acc0);
                acc1 = fmaf(w[8 * jv + 3], a.w, acc1);
                acc0 = fmaf(w[8 * jv + 4], c.x, acc0);
                acc1 = fmaf(w[8 * jv + 5], c.y, acc1);
                acc0 = fmaf(w[8 * jv + 6], c.z, acc0);
                acc1 = fmaf(w[8 * jv + 7], c.w, acc1);
            }
            y = fmaf(DT_STEP, fast_tanh(acc0 + acc1), y_prev);
        }

        y_prev = y;
        out[((size_t)t * N_BATCH + belt) * N_STATE + lane] = y;
    }
}

extern "C" void kernel_launch(void* const* d_in, const int* in_sizes, int n_in,
                              void* d_out, int out_size)
{
    const float* y0     = (const float*)d_in[0];
    const float* forces = (const float*)d_in[1];
    const float* W      = (const float*)d_in[2];
    const float* U      = (const float*)d_in[3];
    const float* b      = (const float*)d_in[4];
    float* out = (float*)d_out;

    dim3 grid(N_BATCH / WARPS_PER_BLOCK);   // 1024 blocks, 8192 warps = 8192 elements
    dim3 block(THREADS_PER_BLOCK);
    recsolve_kernel<<<grid, block>>>(y0, forces, W, U, b, out);
}

// round 2
// speedup vs baseline: 1.5907x; 1.5907x over previous
#include <cuda_runtime.h>
#include <cuda_bf16.h>

// Problem constants (fixed by dataset)
#define N_TIME   64
#define N_BATCH  8192
#define N_STATE  32
#define N_FORCE  16
#define DT_STEP  0.05f
// Picard iterations per implicit step. Contraction ~0.1/iter, warm start err <= 0.05
// => 5 iters -> ~5e-7 per step, ~3e-5 accumulated (gate is 1e-3).
#define PICARD_ITERS 5

#define WARPS_PER_BLOCK 8
#define THREADS_PER_BLOCK (WARPS_PER_BLOCK * 32)
#define ELEMS_PER_WARP 2
#define YSTRIDE 36   // per-element smem stride (padded, 32 floats used)

typedef unsigned long long u64;

// Packed f32x2 FMA (Blackwell): d = a*b + c elementwise on (lo,hi) pairs.
__device__ __forceinline__ u64 fma2(u64 a, u64 b, u64 c) {
    u64 d;
    asm("fma.rn.f32x2 %0, %1, %2, %3;" : "=l"(d) : "l"(a), "l"(b), "l"(c));
    return d;
}
__device__ __forceinline__ u64 pk2(float x, float y) {
    u64 r;
    asm("mov.b64 %0, {%1, %2};" : "=l"(r) : "f"(x), "f"(y));
    return r;
}
__device__ __forceinline__ void upk2(u64 v, float& x, float& y) {
    asm("mov.b64 {%0, %1}, %2;" : "=f"(x), "=f"(y) : "l"(v));
}

// Branchless tanh via exp: abs err ~1e-7 (well under the 1e-3 gate).
__device__ __forceinline__ float fast_tanh(float x) {
    x = fminf(fmaxf(x, -9.0f), 9.0f);
    float e = __expf(2.0f * x);
    return __fdividef(e - 1.0f, e + 1.0f);
}

__global__ __launch_bounds__(THREADS_PER_BLOCK)
void recsolve_kernel(const float* __restrict__ y0,
                     const float* __restrict__ forces,
                     const float* __restrict__ Wmat,
                     const float* __restrict__ Umat,
                     const float* __restrict__ bvec,
                     float* __restrict__ out)
{
    // 2 batch elements per warp: lanes 0-15 -> element A, lanes 16-31 -> element B.
    // Within a half-warp, lane h owns states 2h and 2h+1 (two W rows).
    __shared__ float ysh[WARPS_PER_BLOCK][2][2 * YSTRIDE];  // [warp][dbuf][elem*YSTRIDE]

    const int wib  = threadIdx.x >> 5;
    const int lane = threadIdx.x & 31;
    const int half = lane >> 4;          // which element within the warp
    const int h    = lane & 15;
    const int s0   = 2 * h;              // owned state rows
    const int elt  = (blockIdx.x * WARPS_PER_BLOCK + wib) * ELEMS_PER_WARP + half;

    // W rows s0, s0+1 packed along K as f32x2 pairs (rows are contiguous, 8B-aligned).
    u64 wp0[N_STATE / 2], wp1[N_STATE / 2];
    {
        const u64* W0 = (const u64*)(Wmat + (size_t)s0 * N_STATE);
        const u64* W1 = (const u64*)(Wmat + (size_t)(s0 + 1) * N_STATE);
#pragma unroll
        for (int j = 0; j < N_STATE / 2; j++) { wp0[j] = W0[j]; wp1[j] = W1[j]; }
    }
    // U rows packed along force dim.
    u64 up0[N_FORCE / 2], up1[N_FORCE / 2];
    {
        const u64* U0 = (const u64*)(Umat + (size_t)s0 * N_FORCE);
        const u64* U1 = (const u64*)(Umat + (size_t)(s0 + 1) * N_FORCE);
#pragma unroll
        for (int j = 0; j < N_FORCE / 2; j++) { up0[j] = U0[j]; up1[j] = U1[j]; }
    }
    const float b0 = bvec[s0];
    const float b1 = bvec[s0 + 1];

    float2 yp = *(const float2*)(y0 + (size_t)elt * N_STATE + s0);
    *(float2*)(out + (size_t)elt * N_STATE + s0) = yp;   // out[0] = y0

    float* bufA = ysh[wib][0] + half * YSTRIDE;
    float* bufB = ysh[wib][1] + half * YSTRIDE;

    for (int t = 1; t < N_TIME; t++) {
        // fu = U u_t + b for owned rows (packed along force dim; broadcast LDG).
        const u64* fp = (const u64*)(forces + ((size_t)t * N_BATCH + elt) * N_FORCE);
        u64 a0 = pk2(b0, 0.0f), a1 = pk2(b1, 0.0f);
#pragma unroll
        for (int j = 0; j < N_FORCE / 2; j++) {
            u64 uv = fp[j];
            a0 = fma2(up0[j], uv, a0);
            a1 = fma2(up1[j], uv, a1);
        }
        float fl0, fh0, fl1, fh1;
        upk2(a0, fl0, fh0); upk2(a1, fl1, fh1);
        const float fu0 = fl0 + fh0;
        const float fu1 = fl1 + fh1;

        // Warm-started Picard: y <- y_prev + dt*tanh(W y + fu)
        float yn0 = yp.x, yn1 = yp.y;
#pragma unroll
        for (int it = 0; it < PICARD_ITERS; it++) {
            float* buf = (it & 1) ? bufB : bufA;
            *(float2*)(buf + s0) = make_float2(yn0, yn1);   // STS.64
            __syncwarp();
            const float4* yv = (const float4*)buf;
            u64 acc0 = pk2(fu0, 0.0f), acc1 = pk2(fu1, 0.0f);
#pragma unroll
            for (int jv = 0; jv < N_STATE / 4; jv++) {
                float4 yq = yv[jv];                          // LDS.128 (broadcast/half-warp)
                u64 ylo = pk2(yq.x, yq.y);
                u64 yhi = pk2(yq.z, yq.w);
                acc0 = fma2(wp0[2 * jv],     ylo, acc0);
                acc1 = fma2(wp1[2 * jv],     ylo, acc1);
                acc0 = fma2(wp0[2 * jv + 1], yhi, acc0);
                acc1 = fma2(wp1[2 * jv + 1], yhi, acc1);
            }
            float z0l, z0h, z1l, z1h;
            upk2(acc0, z0l, z0h); upk2(acc1, z1l, z1h);
            yn0 = fmaf(DT_STEP, fast_tanh(z0l + z0h), yp.x);
            yn1 = fmaf(DT_STEP, fast_tanh(z1l + z1h), yp.y);
        }

        yp.x = yn0; yp.y = yn1;
        *(float2*)(out + ((size_t)t * N_BATCH + elt) * N_STATE + s0) = yp;
    }
}

extern "C" void kernel_launch(void* const* d_in, const int* in_sizes, int n_in,
                              void* d_out, int out_size)
{
    const float* y0     = (const float*)d_in[0];
    const float* forces = (const float*)d_in[1];
    const float* W      = (const float*)d_in[2];
    const float* U      = (const float*)d_in[3];
    const float* b      = (const float*)d_in[4];
    float* out = (float*)d_out;

    dim3 grid(N_BATCH / (WARPS_PER_BLOCK * ELEMS_PER_WARP));  // 512 blocks
    dim3 block(THREADS_PER_BLOCK);
    recsolve_kernel<<<grid, block>>>(y0, forces, W, U, b, out);
}

// round 3
// speedup vs baseline: 2.4163x; 1.5190x over previous
#include <cuda_runtime.h>
#include <cuda_bf16.h>

// Problem constants (fixed by dataset)
#define N_TIME   64
#define N_BATCH  8192
#define N_STATE  32
#define N_FORCE  16
#define DT_STEP  0.05f
// Picard iterations per implicit step: first (ITERS-1) use tanh.approx (MUFU),
// final iteration uses accurate tanh, which contracts the approx error by ~c<=0.1.
#define PICARD_ITERS 3

#define WARPS_PER_BLOCK 4
#define THREADS_PER_BLOCK (WARPS_PER_BLOCK * 32)
#define NCHAIN 2                      // independent time-chains interleaved per thread
#define CHAIN_STRIDE (N_BATCH / 2)    // 4096
#define YSTRIDE 36                    // per-element smem stride (padded)

typedef unsigned long long u64;

__device__ __forceinline__ u64 fma2(u64 a, u64 b, u64 c) {
    u64 d;
    asm("fma.rn.f32x2 %0, %1, %2, %3;" : "=l"(d) : "l"(a), "l"(b), "l"(c));
    return d;
}
__device__ __forceinline__ u64 pk2(float x, float y) {
    u64 r;
    asm("mov.b64 %0, {%1, %2};" : "=l"(r) : "f"(x), "f"(y));
    return r;
}
__device__ __forceinline__ void upk2(u64 v, float& x, float& y) {
    asm("mov.b64 {%0, %1}, %2;" : "=f"(x), "=f"(y) : "l"(v));
}

// Fast HW tanh (MUFU), ~1e-3-class accuracy — used for non-final Picard iters only.
__device__ __forceinline__ float tanh_approx(float x) {
    float r;
    asm("tanh.approx.f32 %0, %1;" : "=f"(r) : "f"(x));
    return r;
}
// Accurate tanh (~1e-7 abs): used for the final Picard iteration.
__device__ __forceinline__ float tanh_exact(float x) {
    x = fminf(fmaxf(x, -9.0f), 9.0f);
    float e = __expf(2.0f * x);
    return __fdividef(e - 1.0f, e + 1.0f);
}

__global__ __launch_bounds__(THREADS_PER_BLOCK, 3)
void recsolve_kernel(const float* __restrict__ y0,
                     const float* __restrict__ forces,
                     const float* __restrict__ Wmat,
                     const float* __restrict__ Umat,
                     const float* __restrict__ bvec,
                     float* __restrict__ out)
{
    // Per warp: 2 spatial elements (half-warps) x NCHAIN interleaved batch chains.
    // Lane layout: half = lane>>4 selects spatial element, lane h=lane&15 owns
    // state rows 2h, 2h+1 (W/U registers shared across the interleaved chains).
    __shared__ float ysh[WARPS_PER_BLOCK][2][NCHAIN][2 * YSTRIDE];

    const int wib  = threadIdx.x >> 5;
    const int lane = threadIdx.x & 31;
    const int half = lane >> 4;
    const int h    = lane & 15;
    const int s0   = 2 * h;
    const int base = (blockIdx.x * WARPS_PER_BLOCK + wib) * 2 + half;  // [0, 4096)

    int elt[NCHAIN];
#pragma unroll
    for (int c = 0; c < NCHAIN; c++) elt[c] = base + c * CHAIN_STRIDE;

    // W rows s0, s0+1 packed along K as f32x2 pairs.
    u64 wp0[N_STATE / 2], wp1[N_STATE / 2];
    {
        const u64* W0 = (const u64*)(Wmat + (size_t)s0 * N_STATE);
        const u64* W1 = (const u64*)(Wmat + (size_t)(s0 + 1) * N_STATE);
#pragma unroll
        for (int j = 0; j < N_STATE / 2; j++) { wp0[j] = W0[j]; wp1[j] = W1[j]; }
    }
    u64 up0[N_FORCE / 2], up1[N_FORCE / 2];
    {
        const u64* U0 = (const u64*)(Umat + (size_t)s0 * N_FORCE);
        const u64* U1 = (const u64*)(Umat + (size_t)(s0 + 1) * N_FORCE);
#pragma unroll
        for (int j = 0; j < N_FORCE / 2; j++) { up0[j] = U0[j]; up1[j] = U1[j]; }
    }
    const float b0 = bvec[s0];
    const float b1 = bvec[s0 + 1];

    float2 yp[NCHAIN];
#pragma unroll
    for (int c = 0; c < NCHAIN; c++) {
        yp[c] = *(const float2*)(y0 + (size_t)elt[c] * N_STATE + s0);
        *(float2*)(out + (size_t)elt[c] * N_STATE + s0) = yp[c];   // out[0] = y0
    }

    for (int t = 1; t < N_TIME; t++) {
        // fu = U u_t + b per chain (packed along force dim).
        float fu0[NCHAIN], fu1[NCHAIN];
#pragma unroll
        for (int c = 0; c < NCHAIN; c++) {
            const u64* fp = (const u64*)(forces + ((size_t)t * N_BATCH + elt[c]) * N_FORCE);
            u64 a0 = pk2(b0, 0.0f), a1 = pk2(b1, 0.0f);
#pragma unroll
            for (int j = 0; j < N_FORCE / 2; j++) {
                u64 uv = fp[j];
                a0 = fma2(up0[j], uv, a0);
                a1 = fma2(up1[j], uv, a1);
            }
            float l0, h0, l1, h1;
            upk2(a0, l0, h0); upk2(a1, l1, h1);
            fu0[c] = l0 + h0;
            fu1[c] = l1 + h1;
        }

        // Warm-started Picard: y <- y_prev + dt*tanh(W y + fu)
        float yn0[NCHAIN], yn1[NCHAIN];
#pragma unroll
        for (int c = 0; c < NCHAIN; c++) { yn0[c] = yp[c].x; yn1[c] = yp[c].y; }

#pragma unroll
        for (int it = 0; it < PICARD_ITERS; it++) {
            const int db = it & 1;
#pragma unroll
            for (int c = 0; c < NCHAIN; c++) {
                float* buf = ysh[wib][db][c] + half * YSTRIDE;
                *(float2*)(buf + s0) = make_float2(yn0[c], yn1[c]);   // STS.64
            }
            __syncwarp();

            u64 acc0[NCHAIN], acc1[NCHAIN];
#pragma unroll
            for (int c = 0; c < NCHAIN; c++) {
                acc0[c] = pk2(fu0[c], 0.0f);
                acc1[c] = pk2(fu1[c], 0.0f);
            }
#pragma unroll
            for (int jv = 0; jv < N_STATE / 4; jv++) {
#pragma unroll
                for (int c = 0; c < NCHAIN; c++) {
                    const float4* yv = (const float4*)(ysh[wib][db][c] + half * YSTRIDE);
                    float4 yq = yv[jv];                     // LDS.128 (bcast per half-warp)
                    u64 ylo = pk2(yq.x, yq.y);
                    u64 yhi = pk2(yq.z, yq.w);
                    acc0[c] = fma2(wp0[2 * jv],     ylo, acc0[c]);
                    acc1[c] = fma2(wp1[2 * jv],     ylo, acc1[c]);
                    acc0[c] = fma2(wp0[2 * jv + 1], yhi, acc0[c]);
                    acc1[c] = fma2(wp1[2 * jv + 1], yhi, acc1[c]);
                }
            }
#pragma unroll
            for (int c = 0; c < NCHAIN; c++) {
                float z0l, z0h, z1l, z1h;
                upk2(acc0[c], z0l, z0h); upk2(acc1[c], z1l, z1h);
                const float z0 = z0l + z0h, z1 = z1l + z1h;
                if (it < PICARD_ITERS - 1) {
                    yn0[c] = fmaf(DT_STEP, tanh_approx(z0), yp[c].x);
                    yn1[c] = fmaf(DT_STEP, tanh_approx(z1), yp[c].y);
                } else {
                    yn0[c] = fmaf(DT_STEP, tanh_exact(z0), yp[c].x);
                    yn1[c] = fmaf(DT_STEP, tanh_exact(z1), yp[c].y);
                }
            }
        }

#pragma unroll
        for (int c = 0; c < NCHAIN; c++) {
            yp[c].x = yn0[c]; yp[c].y = yn1[c];
            *(float2*)(out + ((size_t)t * N_BATCH + elt[c]) * N_STATE + s0) = yp[c];
        }
    }
}

extern "C" void kernel_launch(void* const* d_in, const int* in_sizes, int n_in,
                              void* d_out, int out_size)
{
    const float* y0     = (const float*)d_in[0];
    const float* forces = (const float*)d_in[1];
    const float* W      = (const float*)d_in[2];
    const float* U      = (const float*)d_in[3];
    const float* b      = (const float*)d_in[4];
    float* out = (float*)d_out;

    // 512 blocks x 4 warps x (2 spatial x 2 chains) = 8192 elements
    dim3 grid(N_BATCH / (WARPS_PER_BLOCK * 2 * NCHAIN));
    dim3 block(THREADS_PER_BLOCK);
    recsolve_kernel<<<grid, block>>>(y0, forces, W, U, b, out);
}

// round 5
// speedup vs baseline: 2.6886x; 1.1127x over previous
#include <cuda_runtime.h>
#include <cuda_bf16.h>

// Problem constants (fixed by dataset)
#define N_TIME   64
#define N_BATCH  8192
#define N_STATE  32
#define N_FORCE  16
#define DT_STEP  0.05f

#define WARPS_PER_BLOCK 8
#define THREADS_PER_BLOCK (WARPS_PER_BLOCK * 32)
#define YSTRIDE 36   // per-element smem stride (padded)

typedef unsigned long long u64;

__device__ __forceinline__ u64 fma2(u64 a, u64 b, u64 c) {
    u64 d;
    asm("fma.rn.f32x2 %0, %1, %2, %3;" : "=l"(d) : "l"(a), "l"(b), "l"(c));
    return d;
}
__device__ __forceinline__ u64 pk2(float x, float y) {
    u64 r;
    asm("mov.b64 %0, {%1, %2};" : "=l"(r) : "f"(x), "f"(y));
    return r;
}
__device__ __forceinline__ void upk2(u64 v, float& x, float& y) {
    asm("mov.b64 {%0, %1}, %2;" : "=f"(x), "=f"(y) : "l"(v));
}

// HW tanh (MUFU, ~6e-4 abs err): used for predictor + middle iteration.
__device__ __forceinline__ float tanh_approx(float x) {
    float r;
    asm("tanh.approx.f32 %0, %1;" : "=f"(r) : "f"(x));
    return r;
}
// Accurate tanh (~1e-7 abs): final iteration only.
__device__ __forceinline__ float tanh_exact(float x) {
    x = fminf(fmaxf(x, -9.0f), 9.0f);
    float e = __expf(2.0f * x);
    return __fdividef(e - 1.0f, e + 1.0f);
}

// Dot products of smem vector y[0..31] with this lane's two W rows.
// 4 independent fma2 chains (depth 8) -> r0, r1.
__device__ __forceinline__ void matvec_rows(const float* __restrict__ buf,
                                            const u64* __restrict__ wp0,
                                            const u64* __restrict__ wp1,
                                            float& r0, float& r1)
{
    const float4* yv = (const float4*)buf;
    u64 a0a = 0ULL, a0b = 0ULL, a1a = 0ULL, a1b = 0ULL;  // (0.0f,0.0f) bit patterns
#pragma unroll
    for (int jv = 0; jv < N_STATE / 4; jv += 2) {
        float4 q0 = yv[jv];
        float4 q1 = yv[jv + 1];
        u64 lo0 = pk2(q0.x, q0.y), hi0 = pk2(q0.z, q0.w);
        u64 lo1 = pk2(q1.x, q1.y), hi1 = pk2(q1.z, q1.w);
        a0a = fma2(wp0[2 * jv],     lo0, a0a);
        a0b = fma2(wp0[2 * jv + 1], hi0, a0b);
        a1a = fma2(wp1[2 * jv],     lo0, a1a);
        a1b = fma2(wp1[2 * jv + 1], hi0, a1b);
        a0a = fma2(wp0[2 * jv + 2], lo1, a0a);
        a0b = fma2(wp0[2 * jv + 3], hi1, a0b);
        a1a = fma2(wp1[2 * jv + 2], lo1, a1a);
        a1b = fma2(wp1[2 * jv + 3], hi1, a1b);
    }
    float p0, p1, p2, p3, p4, p5, p6, p7;
    upk2(a0a, p0, p1); upk2(a0b, p2, p3);
    upk2(a1a, p4, p5); upk2(a1b, p6, p7);
    r0 = (p0 + p2) + (p1 + p3);
    r1 = (p4 + p6) + (p5 + p7);
}

__global__ __launch_bounds__(THREADS_PER_BLOCK, 2)
void recsolve_kernel(const float* __restrict__ y0,
                     const float* __restrict__ forces,
                     const float* __restrict__ Wmat,
                     const float* __restrict__ Umat,
                     const float* __restrict__ bvec,
                     float* __restrict__ out)
{
    // 2 batch elements per warp (half-warp each); lane h owns state rows 2h, 2h+1.
    __shared__ float ysh[WARPS_PER_BLOCK][2][2 * YSTRIDE];

    const int wib  = threadIdx.x >> 5;
    const int lane = threadIdx.x & 31;
    const int half = lane >> 4;
    const int h    = lane & 15;
    const int s0   = 2 * h;
    const int elt  = (blockIdx.x * WARPS_PER_BLOCK + wib) * 2 + half;

    // W rows s0, s0+1 packed along K as f32x2 pairs.
    u64 wp0[N_STATE / 2], wp1[N_STATE / 2];
    {
        const u64* W0 = (const u64*)(Wmat + (size_t)s0 * N_STATE);
        const u64* W1 = (const u64*)(Wmat + (size_t)(s0 + 1) * N_STATE);
#pragma unroll
        for (int j = 0; j < N_STATE / 2; j++) { wp0[j] = W0[j]; wp1[j] = W1[j]; }
    }
    u64 up0[N_FORCE / 2], up1[N_FORCE / 2];
    {
        const u64* U0 = (const u64*)(Umat + (size_t)s0 * N_FORCE);
        const u64* U1 = (const u64*)(Umat + (size_t)(s0 + 1) * N_FORCE);
#pragma unroll
        for (int j = 0; j < N_FORCE / 2; j++) { up0[j] = U0[j]; up1[j] = U1[j]; }
    }
    const float b0 = bvec[s0];
    const float b1 = bvec[s0 + 1];

    float* buf0 = ysh[wib][0] + half * YSTRIDE;
    float* buf1 = ysh[wib][1] + half * YSTRIDE;

    float2 yp = *(const float2*)(y0 + (size_t)elt * N_STATE + s0);
    *(float2*)(out + (size_t)elt * N_STATE + s0) = yp;   // out[0] = y0

    // Prologue: carried z = W * y0 (exact).
    float z0, z1;
    *(float2*)(buf0 + s0) = yp;
    __syncwarp();
    matvec_rows(buf0, wp0, wp1, z0, z1);

    for (int t = 1; t < N_TIME; t++) {
        // fu = U u_t + b for owned rows.
        const u64* fp = (const u64*)(forces + ((size_t)t * N_BATCH + elt) * N_FORCE);
        u64 a0 = pk2(b0, 0.0f), a1 = pk2(b1, 0.0f);
#pragma unroll
        for (int j = 0; j < N_FORCE / 2; j++) {
            u64 uv = fp[j];
            a0 = fma2(up0[j], uv, a0);
            a1 = fma2(up1[j], uv, a1);
        }
        float l0, hh0, l1, hh1;
        upk2(a0, l0, hh0); upk2(a1, l1, hh1);
        const float fu0 = l0 + hh0;
        const float fu1 = l1 + hh1;

        // Free predictor from carried z (~= W*y_prev): Picard iterate 0, no matvec.
        float yg0 = fmaf(DT_STEP, tanh_approx(z0 + fu0), yp.x);
        float yg1 = fmaf(DT_STEP, tanh_approx(z1 + fu1), yp.y);

        // Iteration 1 (matvec + approx tanh).
        *(float2*)(buf0 + s0) = make_float2(yg0, yg1);
        __syncwarp();
        float g0, g1;
        matvec_rows(buf0, wp0, wp1, g0, g1);
        float y10 = fmaf(DT_STEP, tanh_approx(g0 + fu0), yp.x);
        float y11 = fmaf(DT_STEP, tanh_approx(g1 + fu1), yp.y);

        // Iteration 2 (matvec + exact tanh). The matvec result is carried as z.
        *(float2*)(buf1 + s0) = make_float2(y10, y11);
        __syncwarp();
        matvec_rows(buf1, wp0, wp1, z0, z1);
        yp.x = fmaf(DT_STEP, tanh_exact(z0 + fu0), yp.x);
        yp.y = fmaf(DT_STEP, tanh_exact(z1 + fu1), yp.y);

        *(float2*)(out + ((size_t)t * N_BATCH + elt) * N_STATE + s0) = yp;
    }
}

extern "C" void kernel_launch(void* const* d_in, const int* in_sizes, int n_in,
                              void* d_out, int out_size)
{
    const float* y0     = (const float*)d_in[0];
    const float* forces = (const float*)d_in[1];
    const float* W      = (const float*)d_in[2];
    const float* U      = (const float*)d_in[3];
    const float* b      = (const float*)d_in[4];
    float* out = (float*)d_out;

    dim3 grid(N_BATCH / (WARPS_PER_BLOCK * 2));   // 512 blocks
    dim3 block(THREADS_PER_BLOCK);
    recsolve_kernel<<<grid, block>>>(y0, forces, W, U, b, out);
}